// round 2
// baseline (speedup 1.0000x reference)
#include <cuda_runtime.h>
#include <cstdint>

// ---------------- problem constants ----------------
#define Bn   8
#define Cn   256
#define Hn   64
#define Wn   64
#define HWn  4096            // H*W
#define Mn   32768           // B*H*W (pixel count)
#define Np   3
#define K1   768             // C*Np
#define EPSb 1e-5f

// ---------------- scratch (static device memory; no allocation allowed) ----------------
__device__ __align__(256) float g_off [Bn * 6 * HWn];          // offset conv out (B,6,H,W)
__device__ __align__(256) int   g_sidx[4 * Np * Mn];           // gather indices [corner][n][pixel]
__device__ __align__(256) float g_swgt[4 * Np * Mn];           // bilinear weights
__device__ __align__(256) float g_A   [(size_t)K1 * Mn];       // x_off, K-major: A[k=c*3+n][pixel]
__device__ __align__(256) float g_Wak [K1 * Cn];               // ak_w transposed [k][o]
__device__ __align__(256) float g_Wl1 [Cn * Cn];               // lka1_w transposed [c][o]
__device__ __align__(256) float g_Wcv [Cn * Cn];               // conv_w transposed [c][o]
__device__ __align__(256) float g_w5T [25 * Cn];               // dw5 weights [tap][c]
__device__ __align__(256) float g_w7T [49 * Cn];               // dw7 weights [tap][c]
__device__ __align__(256) float g_pre [(size_t)Mn * Cn];       // ak conv out, NHWC
__device__ __align__(256) float g_y   [(size_t)Mn * Cn];       // after BN+SiLU, NHWC
__device__ __align__(256) float g_t1  [(size_t)Mn * Cn];       // dw5 out
__device__ __align__(256) float g_t2  [(size_t)Mn * Cn];       // dw7 out
__device__ __align__(256) float g_lka [(size_t)Mn * Cn];       // y * attn
__device__ __align__(256) float g_bnp [128 * Cn];              // BN partial sums
__device__ __align__(256) float g_bnp2[128 * Cn];              // BN partial sumsq
__device__ __align__(256) float g_bnsc[Cn];
__device__ __align__(256) float g_bnsh[Cn];

// ---------------- weight prep: transposes for coalesced GEMM / dw access ----------------
__global__ void prep_weights(const float* __restrict__ akw, const float* __restrict__ l1w,
                             const float* __restrict__ cvw, const float* __restrict__ w5,
                             const float* __restrict__ w7)
{
    int i = blockIdx.x * blockDim.x + threadIdx.x;
    if (i < K1 * Cn) {                               // Wak[k][o] = akw[o][c][n], k=c*3+n
        int k = i >> 8, o = i & 255;
        g_Wak[i] = akw[o * K1 + k];
        return;
    }
    int j = i - K1 * Cn;
    if (j < Cn * Cn) { int c = j >> 8, o = j & 255; g_Wl1[j] = l1w[o * Cn + c]; return; }
    j -= Cn * Cn;
    if (j < Cn * Cn) { int c = j >> 8, o = j & 255; g_Wcv[j] = cvw[o * Cn + c]; return; }
    j -= Cn * Cn;
    if (j < 25 * Cn) { int t = j >> 8, c = j & 255; g_w5T[j] = w5[c * 25 + t]; return; }
    j -= 25 * Cn;
    if (j < 49 * Cn) { int t = j >> 8, c = j & 255; g_w7T[j] = w7[c * 49 + t]; return; }
}

// ---------------- offset conv: 256ch -> 6ch, 3x3, pad 1 ----------------
// 128 threads = 128 pixels per block; weights staged in smem in 2 channel-halves.
__global__ __launch_bounds__(128) void offs_kernel(const float* __restrict__ x,
                                                   const float* __restrict__ pw,
                                                   const float* __restrict__ pb,
                                                   float* __restrict__ off)
{
    __shared__ float sw[6 * 128 * 9];     // 27.6 KB
    int tid = threadIdx.x;
    int p = blockIdx.x * 128 + tid;
    int b = p >> 12, hw = p & 4095, h = hw >> 6, w = hw & 63;
    float acc[6];
#pragma unroll
    for (int i = 0; i < 6; i++) acc[i] = pb[i];
    const float* xb = x + (size_t)b * Cn * HWn;

    for (int half = 0; half < 2; half++) {
        __syncthreads();
        for (int i = tid; i < 6 * 128 * 9; i += 128) {
            int t = i % 9, rest = i / 9, cl = rest & 127, oc = rest >> 7;
            sw[i] = pw[(oc * Cn + half * 128 + cl) * 9 + t];
        }
        __syncthreads();
        for (int cl = 0; cl < 128; cl++) {
            const float* xp = xb + (half * 128 + cl) * HWn;
#pragma unroll
            for (int kh = 0; kh < 3; kh++) {
                int hh = h + kh - 1;
                if ((unsigned)hh >= (unsigned)Hn) continue;
#pragma unroll
                for (int kw = 0; kw < 3; kw++) {
                    int w2 = w + kw - 1;
                    if ((unsigned)w2 >= (unsigned)Wn) continue;
                    float v = xp[hh * Wn + w2];
                    int t = kh * 3 + kw;
#pragma unroll
                    for (int oc = 0; oc < 6; oc++)
                        acc[oc] += v * sw[(oc * 128 + cl) * 9 + t];
                }
            }
        }
    }
#pragma unroll
    for (int oc = 0; oc < 6; oc++)
        off[((size_t)b * 6 + oc) * HWn + hw] = acc[oc];
}

// ---------------- per-(pixel,n): bilinear indices + weights ----------------
__global__ void sample_prep(const float* __restrict__ off)
{
    int g = blockIdx.x * blockDim.x + threadIdx.x;
    if (g >= Np * Mn) return;
    int n = g >> 15, p = g & (Mn - 1);
    int b = p >> 12, hw = p & 4095, h = hw >> 6, w = hw & 63;
    const float dxs[3] = {0.f, 0.f, 1.f};
    const float dys[3] = {0.f, 1.f, 0.f};
    float px = (float)h + dxs[n] + off[((size_t)b * 6 + n)     * HWn + hw];
    float py = (float)w + dys[n] + off[((size_t)b * 6 + 3 + n) * HWn + hw];
    float fx = floorf(px), fy = floorf(py);
    float qltx = fminf(fmaxf(fx,       0.f), 63.f);
    float qrbx = fminf(fmaxf(fx + 1.f, 0.f), 63.f);
    float qlty = fminf(fmaxf(fy,       0.f), 63.f);
    float qrby = fminf(fmaxf(fy + 1.f, 0.f), 63.f);
    float pxc  = fminf(fmaxf(px, 0.f), 63.f);
    float pyc  = fminf(fmaxf(py, 0.f), 63.f);
    float glt = (1.f + (qltx - pxc)) * (1.f + (qlty - pyc));
    float grb = (1.f - (qrbx - pxc)) * (1.f - (qrby - pyc));
    float glb = (1.f + (qltx - pxc)) * (1.f - (qrby - pyc));
    float grt = (1.f - (qrbx - pxc)) * (1.f + (qlty - pyc));
    int base = n * Mn + p;
    g_sidx[0 * Np * Mn + base] = (int)qltx * Wn + (int)qlty;  g_swgt[0 * Np * Mn + base] = glt;
    g_sidx[1 * Np * Mn + base] = (int)qrbx * Wn + (int)qrby;  g_swgt[1 * Np * Mn + base] = grb;
    g_sidx[2 * Np * Mn + base] = (int)qltx * Wn + (int)qrby;  g_swgt[2 * Np * Mn + base] = glb;
    g_sidx[3 * Np * Mn + base] = (int)qrbx * Wn + (int)qlty;  g_swgt[3 * Np * Mn + base] = grt;
}

// ---------------- build x_off K-major: A[k=c*3+n][pixel] ----------------
__global__ __launch_bounds__(256) void build_A(const float* __restrict__ x)
{
    int p = blockIdx.x * 256 + threadIdx.x;    // gridDim.x = 128
    int k = blockIdx.y;                        // 0..767
    int c = k / 3, n = k - 3 * c;
    int b = p >> 12;
    const float* xp = x + ((size_t)b * Cn + c) * HWn;
    int base = n * Mn + p;
    float acc = g_swgt[base]                 * xp[g_sidx[base]]
              + g_swgt[Np * Mn + base]       * xp[g_sidx[Np * Mn + base]]
              + g_swgt[2 * Np * Mn + base]   * xp[g_sidx[2 * Np * Mn + base]]
              + g_swgt[3 * Np * Mn + base]   * xp[g_sidx[3 * Np * Mn + base]];
    g_A[(size_t)k * Mn + p] = acc;
}

// ---------------- SGEMM 128x128x8, 256 threads, 8x8 microtile ----------------
// AKM: A stored K-major A[k][m] (lda=M). else A row-major A[m][k] (lda=K).
// EPI 0: C[m][n]=acc   (NHWC store)
// EPI 1: C[m][n]=mulv[m][n]*(acc+bias[n])
// EPI 2: NCHW store with residual: C[(b*256+n)*4096+hw]=acc+bias[n]+addv[same]
template <bool AKM, int EPI>
__global__ __launch_bounds__(256) void sgemm_k(const float* __restrict__ A,
                                               const float* __restrict__ Bm,
                                               float* __restrict__ Cd,
                                               int M, int N, int K,
                                               const float* __restrict__ bias,
                                               const float* __restrict__ mulv,
                                               const float* __restrict__ addv)
{
    __shared__ float As[8][128];
    __shared__ float Bs[8][128];
    int tid = threadIdx.x;
    int m0 = blockIdx.x * 128;
    int n0 = blockIdx.y * 128;
    int tr = tid >> 4, tc = tid & 15;
    float acc[8][8];
#pragma unroll
    for (int i = 0; i < 8; i++)
#pragma unroll
        for (int j = 0; j < 8; j++) acc[i][j] = 0.f;

    for (int k0 = 0; k0 < K; k0 += 8) {
        if (AKM) {
            int kk = tid >> 5, mi = (tid & 31) * 4;
            float4 v = *reinterpret_cast<const float4*>(&A[(size_t)(k0 + kk) * M + m0 + mi]);
            *reinterpret_cast<float4*>(&As[kk][mi]) = v;
        } else {
            int row = tid >> 1, kc = (tid & 1) * 4;
            float4 v = *reinterpret_cast<const float4*>(&A[(size_t)(m0 + row) * K + k0 + kc]);
            As[kc + 0][row] = v.x; As[kc + 1][row] = v.y;
            As[kc + 2][row] = v.z; As[kc + 3][row] = v.w;
        }
        {
            int kk = tid >> 5, ni = (tid & 31) * 4;
            float4 v = *reinterpret_cast<const float4*>(&Bm[(size_t)(k0 + kk) * N + n0 + ni]);
            *reinterpret_cast<float4*>(&Bs[kk][ni]) = v;
        }
        __syncthreads();
#pragma unroll
        for (int kk = 0; kk < 8; kk++) {
            float a[8], bfr[8];
            *reinterpret_cast<float4*>(&a[0])   = *reinterpret_cast<float4*>(&As[kk][tr * 4]);
            *reinterpret_cast<float4*>(&a[4])   = *reinterpret_cast<float4*>(&As[kk][64 + tr * 4]);
            *reinterpret_cast<float4*>(&bfr[0]) = *reinterpret_cast<float4*>(&Bs[kk][tc * 4]);
            *reinterpret_cast<float4*>(&bfr[4]) = *reinterpret_cast<float4*>(&Bs[kk][64 + tc * 4]);
#pragma unroll
            for (int i = 0; i < 8; i++)
#pragma unroll
                for (int j = 0; j < 8; j++)
                    acc[i][j] += a[i] * bfr[j];
        }
        __syncthreads();
    }

#pragma unroll
    for (int i = 0; i < 8; i++) {
        int m = m0 + ((i < 4) ? tr * 4 + i : 64 + tr * 4 + (i - 4));
#pragma unroll
        for (int j = 0; j < 8; j++) {
            int n = n0 + ((j < 4) ? tc * 4 + j : 64 + tc * 4 + (j - 4));
            float v = acc[i][j];
            if (EPI == 0) {
                Cd[(size_t)m * N + n] = v;
            } else if (EPI == 1) {
                v += bias[n];
                Cd[(size_t)m * N + n] = mulv[(size_t)m * N + n] * v;
            } else {
                int bb = m >> 12, hw = m & 4095;
                size_t o = ((size_t)(bb * Cn + n)) * HWn + hw;
                Cd[o] = v + bias[n] + addv[o];
            }
        }
    }
}

// ---------------- BN (batch stats) ----------------
__global__ void bn_part()
{
    int c = threadIdx.x;
    int r0 = blockIdx.x * 256;
    float s = 0.f, s2 = 0.f;
    for (int r = 0; r < 256; r++) {
        float v = g_pre[(size_t)(r0 + r) * Cn + c];
        s += v; s2 += v * v;
    }
    g_bnp [blockIdx.x * Cn + c] = s;
    g_bnp2[blockIdx.x * Cn + c] = s2;
}

__global__ void bn_final(const float* __restrict__ gamma, const float* __restrict__ beta)
{
    int c = threadIdx.x;
    float s = 0.f, s2 = 0.f;
    for (int r = 0; r < 128; r++) { s += g_bnp[r * Cn + c]; s2 += g_bnp2[r * Cn + c]; }
    float mean = s / (float)Mn;
    float var  = s2 / (float)Mn - mean * mean;
    float sc = gamma[c] * rsqrtf(var + EPSb);
    g_bnsc[c] = sc;
    g_bnsh[c] = beta[c] - mean * sc;
}

__global__ void bn_apply()
{
    size_t i = (size_t)blockIdx.x * 256 + threadIdx.x;   // block = one pixel row, tid = channel
    int c = threadIdx.x;
    float v = g_pre[i] * g_bnsc[c] + g_bnsh[c];
    g_y[i] = v / (1.f + expf(-v));                        // SiLU
}

// ---------------- depthwise convs, NHWC, float4 over channels ----------------
// block: 256 threads = 4 pixels x 64 channel-quads
__global__ __launch_bounds__(256) void dw5_kernel(const float* __restrict__ bias)
{
    int q = threadIdx.x & 63, pl = threadIdx.x >> 6;
    int p = blockIdx.x * 4 + pl;
    int b = p >> 12, hw = p & 4095, h = hw >> 6, w = hw & 63;
    int c = q * 4;
    float4 acc = make_float4(bias[c], bias[c + 1], bias[c + 2], bias[c + 3]);
    const float* base = g_y + ((size_t)b << 12) * Cn;
#pragma unroll
    for (int kh = 0; kh < 5; kh++) {
        int hh = h + kh - 2;
        if ((unsigned)hh >= (unsigned)Hn) continue;
#pragma unroll
        for (int kw = 0; kw < 5; kw++) {
            int w2 = w + kw - 2;
            if ((unsigned)w2 >= (unsigned)Wn) continue;
            float4 v  = *reinterpret_cast<const float4*>(&base[(size_t)(hh * Wn + w2) * Cn + c]);
            float4 wv = *reinterpret_cast<const float4*>(&g_w5T[(kh * 5 + kw) * Cn + c]);
            acc.x += v.x * wv.x; acc.y += v.y * wv.y;
            acc.z += v.z * wv.z; acc.w += v.w * wv.w;
        }
    }
    *reinterpret_cast<float4*>(&g_t1[(size_t)p * Cn + c]) = acc;
}

__global__ __launch_bounds__(256) void dw7_kernel(const float* __restrict__ bias)
{
    int q = threadIdx.x & 63, pl = threadIdx.x >> 6;
    int p = blockIdx.x * 4 + pl;
    int b = p >> 12, hw = p & 4095, h = hw >> 6, w = hw & 63;
    int c = q * 4;
    float4 acc = make_float4(bias[c], bias[c + 1], bias[c + 2], bias[c + 3]);
    const float* base = g_t1 + ((size_t)b << 12) * Cn;
#pragma unroll
    for (int kh = 0; kh < 7; kh++) {
        int hh = h + (kh - 3) * 3;
        if ((unsigned)hh >= (unsigned)Hn) continue;
#pragma unroll
        for (int kw = 0; kw < 7; kw++) {
            int w2 = w + (kw - 3) * 3;
            if ((unsigned)w2 >= (unsigned)Wn) continue;
            float4 v  = *reinterpret_cast<const float4*>(&base[(size_t)(hh * Wn + w2) * Cn + c]);
            float4 wv = *reinterpret_cast<const float4*>(&g_w7T[(kh * 7 + kw) * Cn + c]);
            acc.x += v.x * wv.x; acc.y += v.y * wv.y;
            acc.z += v.z * wv.z; acc.w += v.w * wv.w;
        }
    }
    *reinterpret_cast<float4*>(&g_t2[(size_t)p * Cn + c]) = acc;
}

// ---------------- launch ----------------
extern "C" void kernel_launch(void* const* d_in, const int* in_sizes, int n_in,
                              void* d_out, int out_size)
{
    const float* x     = (const float*)d_in[0];
    const float* p_w   = (const float*)d_in[1];
    const float* p_b   = (const float*)d_in[2];
    const float* ak_w  = (const float*)d_in[3];
    const float* gam   = (const float*)d_in[4];
    const float* bet   = (const float*)d_in[5];
    const float* l0w   = (const float*)d_in[6];
    const float* l0b   = (const float*)d_in[7];
    const float* lsw   = (const float*)d_in[8];
    const float* lsb   = (const float*)d_in[9];
    const float* l1w   = (const float*)d_in[10];
    const float* l1b   = (const float*)d_in[11];
    const float* cvw   = (const float*)d_in[12];
    const float* cvb   = (const float*)d_in[13];
    float* out = (float*)d_out;

    float* off_p; cudaGetSymbolAddress((void**)&off_p, g_off);
    float* A_p;   cudaGetSymbolAddress((void**)&A_p,   g_A);
    float* Wak_p; cudaGetSymbolAddress((void**)&Wak_p, g_Wak);
    float* Wl1_p; cudaGetSymbolAddress((void**)&Wl1_p, g_Wl1);
    float* Wcv_p; cudaGetSymbolAddress((void**)&Wcv_p, g_Wcv);
    float* pre_p; cudaGetSymbolAddress((void**)&pre_p, g_pre);
    float* y_p;   cudaGetSymbolAddress((void**)&y_p,   g_y);
    float* t2_p;  cudaGetSymbolAddress((void**)&t2_p,  g_t2);
    float* lka_p; cudaGetSymbolAddress((void**)&lka_p, g_lka);

    int prep_total = K1 * Cn + 2 * Cn * Cn + 25 * Cn + 49 * Cn;
    prep_weights<<<(prep_total + 255) / 256, 256>>>(ak_w, l1w, cvw, l0w, lsw);

    offs_kernel<<<Mn / 128, 128>>>(x, p_w, p_b, off_p);
    sample_prep<<<(Np * Mn + 255) / 256, 256>>>(off_p);
    build_A<<<dim3(Mn / 256, K1), 256>>>(x);

    // ak conv GEMM: [32768 x 768] (K-major A) @ [768 x 256] -> g_pre (NHWC)
    sgemm_k<true, 0><<<dim3(Mn / 128, Cn / 128), 256>>>(A_p, Wak_p, pre_p,
                                                        Mn, Cn, K1, nullptr, nullptr, nullptr);
    bn_part<<<128, 256>>>();
    bn_final<<<1, 256>>>(gam, bet);
    bn_apply<<<Mn, 256>>>();

    dw5_kernel<<<Mn / 4, 256>>>(l0b);
    dw7_kernel<<<Mn / 4, 256>>>(lsb);

    // lka1 1x1 GEMM with fused (u * attn) epilogue -> g_lka
    sgemm_k<false, 1><<<dim3(Mn / 128, Cn / 128), 256>>>(t2_p, Wl1_p, lka_p,
                                                         Mn, Cn, Cn, l1b, y_p, nullptr);
    // final 1x1 GEMM, fused bias + residual, NCHW store -> d_out
    sgemm_k<false, 2><<<dim3(Mn / 128, Cn / 128), 256>>>(lka_p, Wcv_p, out,
                                                         Mn, Cn, Cn, cvb, nullptr, (float*)x);
}

// round 8
// speedup vs baseline: 1.1731x; 1.1731x over previous
#include <cuda_runtime.h>
#include <cuda_bf16.h>
#include <cstdint>

// ---------------- problem constants ----------------
#define Bn   8
#define Cn   256
#define Hn   64
#define Wn   64
#define HWn  4096
#define Mn   32768           // B*H*W
#define Np   3
#define K1   768             // C*Np
#define EPSb 1e-5f

// ---------------- scratch ----------------
__device__ __align__(256) float g_off [Bn * 6 * HWn];
__device__ __align__(256) int   g_sidx[4 * Np * Mn];
__device__ __align__(256) float g_swgt[4 * Np * Mn];
__device__ __align__(256) float g_A   [(size_t)K1 * Mn];     // x_off K-major [k][m]
__device__ __align__(256) float g_At  [(size_t)Mn * K1];     // x_off row-major [m][k]
__device__ __align__(256) float g_w5T [25 * Cn];
__device__ __align__(256) float g_w7T [49 * Cn];
__device__ __align__(256) float g_pre [(size_t)Mn * Cn];
__device__ __align__(256) float g_y   [(size_t)Mn * Cn];
__device__ __align__(256) float g_t1  [(size_t)Mn * Cn];
__device__ __align__(256) float g_t2  [(size_t)Mn * Cn];
__device__ __align__(256) float g_lka [(size_t)Mn * Cn];
__device__ __align__(256) float g_bnp [128 * Cn];
__device__ __align__(256) float g_bnp2[128 * Cn];
__device__ __align__(256) float g_bnsc[Cn];
__device__ __align__(256) float g_bnsh[Cn];

// ---------------- small prep ----------------
__global__ void prep_weights(const float* __restrict__ w5, const float* __restrict__ w7)
{
    int i = blockIdx.x * blockDim.x + threadIdx.x;
    if (i < 25 * Cn) { int t = i >> 8, c = i & 255; g_w5T[i] = w5[c * 25 + t]; return; }
    int j = i - 25 * Cn;
    if (j < 49 * Cn) { int t = j >> 8, c = j & 255; g_w7T[j] = w7[c * 49 + t]; return; }
}

// ---------------- offset conv: 256ch -> 6ch, 3x3, pad 1 ----------------
__global__ __launch_bounds__(128) void offs_kernel(const float* __restrict__ x,
                                                   const float* __restrict__ pw,
                                                   const float* __restrict__ pb,
                                                   float* __restrict__ off)
{
    __shared__ float sw[6 * 128 * 9];
    int tid = threadIdx.x;
    int p = blockIdx.x * 128 + tid;
    int b = p >> 12, hw = p & 4095, h = hw >> 6, w = hw & 63;
    float acc[6];
#pragma unroll
    for (int i = 0; i < 6; i++) acc[i] = pb[i];
    const float* xb = x + (size_t)b * Cn * HWn;
    for (int half = 0; half < 2; half++) {
        __syncthreads();
        for (int i = tid; i < 6 * 128 * 9; i += 128) {
            int t = i % 9, rest = i / 9, cl = rest & 127, oc = rest >> 7;
            sw[i] = pw[(oc * Cn + half * 128 + cl) * 9 + t];
        }
        __syncthreads();
        for (int cl = 0; cl < 128; cl++) {
            const float* xp = xb + (half * 128 + cl) * HWn;
#pragma unroll
            for (int kh = 0; kh < 3; kh++) {
                int hh = h + kh - 1;
                if ((unsigned)hh >= (unsigned)Hn) continue;
#pragma unroll
                for (int kw = 0; kw < 3; kw++) {
                    int w2 = w + kw - 1;
                    if ((unsigned)w2 >= (unsigned)Wn) continue;
                    float v = xp[hh * Wn + w2];
                    int t = kh * 3 + kw;
#pragma unroll
                    for (int oc = 0; oc < 6; oc++)
                        acc[oc] += v * sw[(oc * 128 + cl) * 9 + t];
                }
            }
        }
    }
#pragma unroll
    for (int oc = 0; oc < 6; oc++)
        off[((size_t)b * 6 + oc) * HWn + hw] = acc[oc];
}

// ---------------- bilinear prep ----------------
__global__ void sample_prep(const float* __restrict__ off)
{
    int g = blockIdx.x * blockDim.x + threadIdx.x;
    if (g >= Np * Mn) return;
    int n = g >> 15, p = g & (Mn - 1);
    int b = p >> 12, hw = p & 4095, h = hw >> 6, w = hw & 63;
    const float dxs[3] = {0.f, 0.f, 1.f};
    const float dys[3] = {0.f, 1.f, 0.f};
    float px = (float)h + dxs[n] + off[((size_t)b * 6 + n)     * HWn + hw];
    float py = (float)w + dys[n] + off[((size_t)b * 6 + 3 + n) * HWn + hw];
    float fx = floorf(px), fy = floorf(py);
    float qltx = fminf(fmaxf(fx,       0.f), 63.f);
    float qrbx = fminf(fmaxf(fx + 1.f, 0.f), 63.f);
    float qlty = fminf(fmaxf(fy,       0.f), 63.f);
    float qrby = fminf(fmaxf(fy + 1.f, 0.f), 63.f);
    float pxc  = fminf(fmaxf(px, 0.f), 63.f);
    float pyc  = fminf(fmaxf(py, 0.f), 63.f);
    float glt = (1.f + (qltx - pxc)) * (1.f + (qlty - pyc));
    float grb = (1.f - (qrbx - pxc)) * (1.f - (qrby - pyc));
    float glb = (1.f + (qltx - pxc)) * (1.f - (qrby - pyc));
    float grt = (1.f - (qrbx - pxc)) * (1.f + (qlty - pyc));
    int base = n * Mn + p;
    g_sidx[0 * Np * Mn + base] = (int)qltx * Wn + (int)qlty;  g_swgt[0 * Np * Mn + base] = glt;
    g_sidx[1 * Np * Mn + base] = (int)qrbx * Wn + (int)qrby;  g_swgt[1 * Np * Mn + base] = grb;
    g_sidx[2 * Np * Mn + base] = (int)qltx * Wn + (int)qrby;  g_swgt[2 * Np * Mn + base] = glb;
    g_sidx[3 * Np * Mn + base] = (int)qrbx * Wn + (int)qlty;  g_swgt[3 * Np * Mn + base] = grt;
}

// ---------------- build x_off K-major ----------------
__global__ __launch_bounds__(256) void build_A(const float* __restrict__ x)
{
    int p = blockIdx.x * 256 + threadIdx.x;
    int k = blockIdx.y;
    int c = k / 3, n = k - 3 * c;
    int b = p >> 12;
    const float* xp = x + ((size_t)b * Cn + c) * HWn;
    int base = n * Mn + p;
    float acc = g_swgt[base]               * xp[g_sidx[base]]
              + g_swgt[Np * Mn + base]     * xp[g_sidx[Np * Mn + base]]
              + g_swgt[2 * Np * Mn + base] * xp[g_sidx[2 * Np * Mn + base]]
              + g_swgt[3 * Np * Mn + base] * xp[g_sidx[3 * Np * Mn + base]];
    g_A[(size_t)k * Mn + p] = acc;
}

// ---------------- transpose g_A[k][m] -> g_At[m][k] ----------------
__global__ __launch_bounds__(256) void transpose_A()
{
    __shared__ float t[32][33];
    int mb = blockIdx.x, kb = blockIdx.y;
    int tx = threadIdx.x & 31, ty = threadIdx.x >> 5;
#pragma unroll
    for (int i = 0; i < 32; i += 8)
        t[ty + i][tx] = g_A[(size_t)(kb * 32 + ty + i) * Mn + mb * 32 + tx];
    __syncthreads();
#pragma unroll
    for (int i = 0; i < 32; i += 8)
        g_At[(size_t)(mb * 32 + ty + i) * K1 + kb * 32 + tx] = t[tx][ty + i];
}

// ---------------- bf16 split helpers ----------------
__device__ __forceinline__ uint32_t pack_bf2(__nv_bfloat16 a, __nv_bfloat16 b) {
    __nv_bfloat162 t = __halves2bfloat162(a, b);
    return *reinterpret_cast<uint32_t*>(&t);
}
__device__ __forceinline__ void cvt_hilo4(float4 v, uint32_t* hi, uint32_t* lo) {
    __nv_bfloat16 hx = __float2bfloat16_rn(v.x);
    __nv_bfloat16 hy = __float2bfloat16_rn(v.y);
    __nv_bfloat16 hz = __float2bfloat16_rn(v.z);
    __nv_bfloat16 hw = __float2bfloat16_rn(v.w);
    hi[0] = pack_bf2(hx, hy);
    hi[1] = pack_bf2(hz, hw);
    lo[0] = pack_bf2(__float2bfloat16_rn(v.x - __bfloat162float(hx)),
                     __float2bfloat16_rn(v.y - __bfloat162float(hy)));
    lo[1] = pack_bf2(__float2bfloat16_rn(v.z - __bfloat162float(hz)),
                     __float2bfloat16_rn(v.w - __bfloat162float(hw)));
}
__device__ __forceinline__ void mma_bf16(float* c, const uint32_t* a, const uint32_t* b) {
    asm volatile(
        "mma.sync.aligned.m16n8k16.row.col.f32.bf16.bf16.f32 "
        "{%0,%1,%2,%3}, {%4,%5,%6,%7}, {%8,%9}, {%0,%1,%2,%3};"
        : "+f"(c[0]), "+f"(c[1]), "+f"(c[2]), "+f"(c[3])
        : "r"(a[0]), "r"(a[1]), "r"(a[2]), "r"(a[3]), "r"(b[0]), "r"(b[1]));
}

// ---------------- mma.sync bf16 split GEMM: tile 128x128, K-chunk 32 ----------------
// D[m][n] = sum_k A[m][k]*Bw[n][k], A row-major [M x K], Bw row-major [N=256 x K].
// EPI 0: row-major store. EPI 1: Cd = mulv*(acc+bias). EPI 2: NCHW + bias + residual.
#define SROW 40     // bf16 units per smem row (80B stride -> conflict-free frags)

template <int EPI>
__global__ __launch_bounds__(256) void mma_gemm(const float* __restrict__ A,
                                                const float* __restrict__ Bw,
                                                float* __restrict__ Cd, int K,
                                                const float* __restrict__ bias,
                                                const float* __restrict__ mulv,
                                                const float* __restrict__ addv)
{
    __shared__ __nv_bfloat16 As_hi[128 * SROW];
    __shared__ __nv_bfloat16 As_lo[128 * SROW];
    __shared__ __nv_bfloat16 Bs_hi[128 * SROW];
    __shared__ __nv_bfloat16 Bs_lo[128 * SROW];

    const int tid  = threadIdx.x;
    const int lane = tid & 31;
    const int wrp  = tid >> 5;
    const int wm   = wrp >> 1;          // 0..3  (m quadrant, 32 rows)
    const int wn   = wrp & 1;           // 0..1  (n half, 64 cols)
    const int g    = lane >> 2;         // 0..7
    const int t2   = (lane & 3) * 2;    // 0,2,4,6
    const int m0   = blockIdx.x * 128;
    const int n0   = blockIdx.y * 128;

    const int srow = tid >> 1;                // staging row 0..127
    const int skb  = (tid & 1) * 16;          // staging k-base 0 or 16

    float acc[2][8][4];
#pragma unroll
    for (int i = 0; i < 2; i++)
#pragma unroll
        for (int j = 0; j < 8; j++)
#pragma unroll
            for (int q = 0; q < 4; q++) acc[i][j][q] = 0.f;

    float4 pa[4], pb[4];
    const int NCH = K >> 5;

    // prefetch chunk 0
#pragma unroll
    for (int j = 0; j < 4; j++) {
        pa[j] = *reinterpret_cast<const float4*>(&A [(size_t)(m0 + srow) * K + skb + j * 4]);
        pb[j] = *reinterpret_cast<const float4*>(&Bw[(size_t)(n0 + srow) * K + skb + j * 4]);
    }

    for (int ch = 0; ch < NCH; ch++) {
        __syncthreads();                       // consumers of previous chunk done
#pragma unroll
        for (int j = 0; j < 4; j++) {
            uint32_t hi[2], lo[2];
            int off = srow * SROW + skb + j * 4;
            cvt_hilo4(pa[j], hi, lo);
            *reinterpret_cast<uint2*>(&As_hi[off]) = make_uint2(hi[0], hi[1]);
            *reinterpret_cast<uint2*>(&As_lo[off]) = make_uint2(lo[0], lo[1]);
            cvt_hilo4(pb[j], hi, lo);
            *reinterpret_cast<uint2*>(&Bs_hi[off]) = make_uint2(hi[0], hi[1]);
            *reinterpret_cast<uint2*>(&Bs_lo[off]) = make_uint2(lo[0], lo[1]);
        }
        __syncthreads();

        if (ch + 1 < NCH) {                    // prefetch next chunk (in flight during mma)
            int k0 = (ch + 1) << 5;
#pragma unroll
            for (int j = 0; j < 4; j++) {
                pa[j] = *reinterpret_cast<const float4*>(&A [(size_t)(m0 + srow) * K + k0 + skb + j * 4]);
                pb[j] = *reinterpret_cast<const float4*>(&Bw[(size_t)(n0 + srow) * K + k0 + skb + j * 4]);
            }
        }

#pragma unroll
        for (int ks = 0; ks < 2; ks++) {
            const int kk = ks * 16 + t2;       // fragment k offset
            uint32_t ah[2][4], al[2][4];
#pragma unroll
            for (int mt = 0; mt < 2; mt++) {
                int r = wm * 32 + mt * 16 + g;
                ah[mt][0] = *reinterpret_cast<const uint32_t*>(&As_hi[ r      * SROW + kk    ]);
                ah[mt][1] = *reinterpret_cast<const uint32_t*>(&As_hi[(r + 8) * SROW + kk    ]);
                ah[mt][2] = *reinterpret_cast<const uint32_t*>(&As_hi[ r      * SROW + kk + 8]);
                ah[mt][3] = *reinterpret_cast<const uint32_t*>(&As_hi[(r + 8) * SROW + kk + 8]);
                al[mt][0] = *reinterpret_cast<const uint32_t*>(&As_lo[ r      * SROW + kk    ]);
                al[mt][1] = *reinterpret_cast<const uint32_t*>(&As_lo[(r + 8) * SROW + kk    ]);
                al[mt][2] = *reinterpret_cast<const uint32_t*>(&As_lo[ r      * SROW + kk + 8]);
                al[mt][3] = *reinterpret_cast<const uint32_t*>(&As_lo[(r + 8) * SROW + kk + 8]);
            }
#pragma unroll
            for (int nt = 0; nt < 8; nt++) {
                int n = wn * 64 + nt * 8 + g;
                uint32_t bh[2], bl[2];
                bh[0] = *reinterpret_cast<const uint32_t*>(&Bs_hi[n * SROW + kk    ]);
                bh[1] = *reinterpret_cast<const uint32_t*>(&Bs_hi[n * SROW + kk + 8]);
                bl[0] = *reinterpret_cast<const uint32_t*>(&Bs_lo[n * SROW + kk    ]);
                bl[1] = *reinterpret_cast<const uint32_t*>(&Bs_lo[n * SROW + kk + 8]);
#pragma unroll
                for (int mt = 0; mt < 2; mt++) {
                    mma_bf16(acc[mt][nt], ah[mt], bh);
                    mma_bf16(acc[mt][nt], ah[mt], bl);
                    mma_bf16(acc[mt][nt], al[mt], bh);
                }
            }
        }
    }

    // ---------------- epilogue ----------------
#pragma unroll
    for (int mt = 0; mt < 2; mt++) {
        int mrow = m0 + wm * 32 + mt * 16 + g;           // rows mrow, mrow+8
#pragma unroll
        for (int nt = 0; nt < 8; nt++) {
            int ncol = n0 + wn * 64 + nt * 8 + t2;
            float c0 = acc[mt][nt][0], c1 = acc[mt][nt][1];
            float c2 = acc[mt][nt][2], c3 = acc[mt][nt][3];
            if (EPI == 0) {
                *reinterpret_cast<float2*>(&Cd[(size_t) mrow      * Cn + ncol]) = make_float2(c0, c1);
                *reinterpret_cast<float2*>(&Cd[(size_t)(mrow + 8) * Cn + ncol]) = make_float2(c2, c3);
            } else if (EPI == 1) {
                float b0 = bias[ncol], b1 = bias[ncol + 1];
                float2 u0 = *reinterpret_cast<const float2*>(&mulv[(size_t) mrow      * Cn + ncol]);
                float2 u1 = *reinterpret_cast<const float2*>(&mulv[(size_t)(mrow + 8) * Cn + ncol]);
                *reinterpret_cast<float2*>(&Cd[(size_t) mrow      * Cn + ncol]) =
                    make_float2(u0.x * (c0 + b0), u0.y * (c1 + b1));
                *reinterpret_cast<float2*>(&Cd[(size_t)(mrow + 8) * Cn + ncol]) =
                    make_float2(u1.x * (c2 + b0), u1.y * (c3 + b1));
            } else {
                float b0 = bias[ncol], b1 = bias[ncol + 1];
                int bq = mrow >> 12, hw = mrow & 4095;
                size_t o0 = ((size_t)(bq * Cn + ncol)) * HWn + hw;
                size_t o1 = o0 + HWn;                    // ncol+1
                Cd[o0]     = c0 + b0 + addv[o0];
                Cd[o1]     = c1 + b1 + addv[o1];
                Cd[o0 + 8] = c2 + b0 + addv[o0 + 8];     // row mrow+8 -> hw+8
                Cd[o1 + 8] = c3 + b1 + addv[o1 + 8];
            }
        }
    }
}

// ---------------- BN (batch stats) ----------------
__global__ void bn_part()
{
    int c = threadIdx.x;
    int r0 = blockIdx.x * 256;
    float s = 0.f, s2 = 0.f;
    for (int r = 0; r < 256; r++) {
        float v = g_pre[(size_t)(r0 + r) * Cn + c];
        s += v; s2 += v * v;
    }
    g_bnp [blockIdx.x * Cn + c] = s;
    g_bnp2[blockIdx.x * Cn + c] = s2;
}

__global__ void bn_final(const float* __restrict__ gamma, const float* __restrict__ beta)
{
    int c = threadIdx.x;
    float s = 0.f, s2 = 0.f;
    for (int r = 0; r < 128; r++) { s += g_bnp[r * Cn + c]; s2 += g_bnp2[r * Cn + c]; }
    float mean = s / (float)Mn;
    float var  = s2 / (float)Mn - mean * mean;
    float sc = gamma[c] * rsqrtf(var + EPSb);
    g_bnsc[c] = sc;
    g_bnsh[c] = beta[c] - mean * sc;
}

__global__ void bn_apply()
{
    size_t i = (size_t)blockIdx.x * 256 + threadIdx.x;
    int c = threadIdx.x;
    float v = g_pre[i] * g_bnsc[c] + g_bnsh[c];
    g_y[i] = v / (1.f + expf(-v));
}

// ---------------- depthwise convs ----------------
__global__ __launch_bounds__(256) void dw5_kernel(const float* __restrict__ bias)
{
    int q = threadIdx.x & 63, pl = threadIdx.x >> 6;
    int p = blockIdx.x * 4 + pl;
    int b = p >> 12, hw = p & 4095, h = hw >> 6, w = hw & 63;
    int c = q * 4;
    float4 acc = make_float4(bias[c], bias[c + 1], bias[c + 2], bias[c + 3]);
    const float* base = g_y + ((size_t)b << 12) * Cn;
#pragma unroll
    for (int kh = 0; kh < 5; kh++) {
        int hh = h + kh - 2;
        if ((unsigned)hh >= (unsigned)Hn) continue;
#pragma unroll
        for (int kw = 0; kw < 5; kw++) {
            int w2 = w + kw - 2;
            if ((unsigned)w2 >= (unsigned)Wn) continue;
            float4 v  = *reinterpret_cast<const float4*>(&base[(size_t)(hh * Wn + w2) * Cn + c]);
            float4 wv = *reinterpret_cast<const float4*>(&g_w5T[(kh * 5 + kw) * Cn + c]);
            acc.x += v.x * wv.x; acc.y += v.y * wv.y;
            acc.z += v.z * wv.z; acc.w += v.w * wv.w;
        }
    }
    *reinterpret_cast<float4*>(&g_t1[(size_t)p * Cn + c]) = acc;
}

__global__ __launch_bounds__(256) void dw7_kernel(const float* __restrict__ bias)
{
    int q = threadIdx.x & 63, pl = threadIdx.x >> 6;
    int p = blockIdx.x * 4 + pl;
    int b = p >> 12, hw = p & 4095, h = hw >> 6, w = hw & 63;
    int c = q * 4;
    float4 acc = make_float4(bias[c], bias[c + 1], bias[c + 2], bias[c + 3]);
    const float* base = g_t1 + ((size_t)b << 12) * Cn;
#pragma unroll
    for (int kh = 0; kh < 7; kh++) {
        int hh = h + (kh - 3) * 3;
        if ((unsigned)hh >= (unsigned)Hn) continue;
#pragma unroll
        for (int kw = 0; kw < 7; kw++) {
            int w2 = w + (kw - 3) * 3;
            if ((unsigned)w2 >= (unsigned)Wn) continue;
            float4 v  = *reinterpret_cast<const float4*>(&base[(size_t)(hh * Wn + w2) * Cn + c]);
            float4 wv = *reinterpret_cast<const float4*>(&g_w7T[(kh * 7 + kw) * Cn + c]);
            acc.x += v.x * wv.x; acc.y += v.y * wv.y;
            acc.z += v.z * wv.z; acc.w += v.w * wv.w;
        }
    }
    *reinterpret_cast<float4*>(&g_t2[(size_t)p * Cn + c]) = acc;
}

// ---------------- launch ----------------
extern "C" void kernel_launch(void* const* d_in, const int* in_sizes, int n_in,
                              void* d_out, int out_size)
{
    const float* x   = (const float*)d_in[0];
    const float* p_w = (const float*)d_in[1];
    const float* p_b = (const float*)d_in[2];
    const float* akw = (const float*)d_in[3];
    const float* gam = (const float*)d_in[4];
    const float* bet = (const float*)d_in[5];
    const float* l0w = (const float*)d_in[6];
    const float* l0b = (const float*)d_in[7];
    const float* lsw = (const float*)d_in[8];
    const float* lsb = (const float*)d_in[9];
    const float* l1w = (const float*)d_in[10];
    const float* l1b = (const float*)d_in[11];
    const float* cvw = (const float*)d_in[12];
    const float* cvb = (const float*)d_in[13];
    float* out = (float*)d_out;

    float* off_p; cudaGetSymbolAddress((void**)&off_p, g_off);
    float* At_p;  cudaGetSymbolAddress((void**)&At_p,  g_At);
    float* pre_p; cudaGetSymbolAddress((void**)&pre_p, g_pre);
    float* y_p;   cudaGetSymbolAddress((void**)&y_p,   g_y);
    float* t2_p;  cudaGetSymbolAddress((void**)&t2_p,  g_t2);
    float* lka_p; cudaGetSymbolAddress((void**)&lka_p, g_lka);

    prep_weights<<<(25 * Cn + 49 * Cn + 255) / 256, 256>>>(l0w, lsw);
    offs_kernel<<<Mn / 128, 128>>>(x, p_w, p_b, off_p);
    sample_prep<<<(Np * Mn + 255) / 256, 256>>>(off_p);
    build_A<<<dim3(Mn / 256, K1), 256>>>(x);
    transpose_A<<<dim3(Mn / 32, K1 / 32), 256>>>();

    // GEMM1: pre[m][o] = sum_k xoff[m][k] * akw[o][k]   (K=768)
    mma_gemm<0><<<dim3(Mn / 128, Cn / 128), 256>>>(At_p, akw, pre_p, K1,
                                                   nullptr, nullptr, nullptr);
    bn_part<<<128, 256>>>();
    bn_final<<<1, 256>>>(gam, bet);
    bn_apply<<<Mn, 256>>>();

    dw5_kernel<<<Mn / 4, 256>>>(l0b);
    dw7_kernel<<<Mn / 4, 256>>>(lsb);

    // GEMM2: lka = y * (t2 @ l1w^T + b)   (K=256)
    mma_gemm<1><<<dim3(Mn / 128, Cn / 128), 256>>>(t2_p, l1w, lka_p, Cn,
                                                   l1b, y_p, nullptr);
    // GEMM3: out = lka @ cvw^T + b + x   (NCHW, K=256)
    mma_gemm<2><<<dim3(Mn / 128, Cn / 128), 256>>>(lka_p, cvw, out, Cn,
                                                   cvb, nullptr, (float*)x);
}

// round 10
// speedup vs baseline: 1.2961x; 1.1048x over previous
#include <cuda_runtime.h>
#include <cuda_bf16.h>
#include <cstdint>

// ---------------- problem constants ----------------
#define Bn   8
#define Cn   256
#define Hn   64
#define Wn   64
#define HWn  4096
#define Mn   32768           // B*H*W
#define Np   3
#define K1   768             // C*Np
#define EPSb 1e-5f

// ---------------- scratch ----------------
__device__ __align__(256) float g_off [Bn * 6 * HWn];
__device__ __align__(256) int   g_sidx[4 * Np * Mn];
__device__ __align__(256) float g_swgt[4 * Np * Mn];
__device__ __align__(256) float g_At  [(size_t)Mn * K1];     // x_off row-major [m][k]
__device__ __align__(256) float g_w5T [25 * Cn];
__device__ __align__(256) float g_w7T [49 * Cn];
__device__ __align__(256) float g_pre [(size_t)Mn * Cn];
__device__ __align__(256) float g_y   [(size_t)Mn * Cn];
__device__ __align__(256) float g_t1  [(size_t)Mn * Cn];
__device__ __align__(256) float g_t2  [(size_t)Mn * Cn];
__device__ __align__(256) float g_lka [(size_t)Mn * Cn];
__device__ __align__(256) float g_bnp [128 * Cn];
__device__ __align__(256) float g_bnp2[128 * Cn];
__device__ __align__(256) float g_bnsc[Cn];
__device__ __align__(256) float g_bnsh[Cn];

__device__ __forceinline__ uint32_t smem_u32(const void* p) {
    uint32_t a;
    asm("{ .reg .u64 t; cvta.to.shared.u64 t, %1; cvt.u32.u64 %0, t; }" : "=r"(a) : "l"(p));
    return a;
}

// ---------------- small prep ----------------
__global__ void prep_weights(const float* __restrict__ w5, const float* __restrict__ w7)
{
    int i = blockIdx.x * blockDim.x + threadIdx.x;
    if (i < 25 * Cn) { int t = i >> 8, c = i & 255; g_w5T[i] = w5[c * 25 + t]; return; }
    int j = i - 25 * Cn;
    if (j < 49 * Cn) { int t = j >> 8, c = j & 255; g_w7T[j] = w7[c * 49 + t]; return; }
}

// ---------------- offset conv: 256ch -> 6ch, 3x3, pad 1 ----------------
__global__ __launch_bounds__(128) void offs_kernel(const float* __restrict__ x,
                                                   const float* __restrict__ pw,
                                                   const float* __restrict__ pb,
                                                   float* __restrict__ off)
{
    __shared__ float sw[6 * 128 * 9];
    int tid = threadIdx.x;
    int p = blockIdx.x * 128 + tid;
    int b = p >> 12, hw = p & 4095, h = hw >> 6, w = hw & 63;
    float acc[6];
#pragma unroll
    for (int i = 0; i < 6; i++) acc[i] = pb[i];
    const float* xb = x + (size_t)b * Cn * HWn;
    for (int half = 0; half < 2; half++) {
        __syncthreads();
        for (int i = tid; i < 6 * 128 * 9; i += 128) {
            int t = i % 9, rest = i / 9, cl = rest & 127, oc = rest >> 7;
            sw[i] = pw[(oc * Cn + half * 128 + cl) * 9 + t];
        }
        __syncthreads();
        for (int cl = 0; cl < 128; cl++) {
            const float* xp = xb + (half * 128 + cl) * HWn;
#pragma unroll
            for (int kh = 0; kh < 3; kh++) {
                int hh = h + kh - 1;
                if ((unsigned)hh >= (unsigned)Hn) continue;
#pragma unroll
                for (int kw = 0; kw < 3; kw++) {
                    int w2 = w + kw - 1;
                    if ((unsigned)w2 >= (unsigned)Wn) continue;
                    float v = xp[hh * Wn + w2];
                    int t = kh * 3 + kw;
#pragma unroll
                    for (int oc = 0; oc < 6; oc++)
                        acc[oc] += v * sw[(oc * 128 + cl) * 9 + t];
                }
            }
        }
    }
#pragma unroll
    for (int oc = 0; oc < 6; oc++)
        off[((size_t)b * 6 + oc) * HWn + hw] = acc[oc];
}

// ---------------- bilinear prep ----------------
__global__ void sample_prep(const float* __restrict__ off)
{
    int g = blockIdx.x * blockDim.x + threadIdx.x;
    if (g >= Np * Mn) return;
    int n = g >> 15, p = g & (Mn - 1);
    int b = p >> 12, hw = p & 4095, h = hw >> 6, w = hw & 63;
    const float dxs[3] = {0.f, 0.f, 1.f};
    const float dys[3] = {0.f, 1.f, 0.f};
    float px = (float)h + dxs[n] + off[((size_t)b * 6 + n)     * HWn + hw];
    float py = (float)w + dys[n] + off[((size_t)b * 6 + 3 + n) * HWn + hw];
    float fx = floorf(px), fy = floorf(py);
    float qltx = fminf(fmaxf(fx,       0.f), 63.f);
    float qrbx = fminf(fmaxf(fx + 1.f, 0.f), 63.f);
    float qlty = fminf(fmaxf(fy,       0.f), 63.f);
    float qrby = fminf(fmaxf(fy + 1.f, 0.f), 63.f);
    float pxc  = fminf(fmaxf(px, 0.f), 63.f);
    float pyc  = fminf(fmaxf(py, 0.f), 63.f);
    float glt = (1.f + (qltx - pxc)) * (1.f + (qlty - pyc));
    float grb = (1.f - (qrbx - pxc)) * (1.f - (qrby - pyc));
    float glb = (1.f + (qltx - pxc)) * (1.f - (qrby - pyc));
    float grt = (1.f - (qrbx - pxc)) * (1.f + (qlty - pyc));
    int base = n * Mn + p;
    g_sidx[0 * Np * Mn + base] = (int)qltx * Wn + (int)qlty;  g_swgt[0 * Np * Mn + base] = glt;
    g_sidx[1 * Np * Mn + base] = (int)qrbx * Wn + (int)qrby;  g_swgt[1 * Np * Mn + base] = grb;
    g_sidx[2 * Np * Mn + base] = (int)qltx * Wn + (int)qrby;  g_swgt[2 * Np * Mn + base] = glb;
    g_sidx[3 * Np * Mn + base] = (int)qrbx * Wn + (int)qlty;  g_swgt[3 * Np * Mn + base] = grt;
}

// ---------------- fused gather + transpose: write g_At[m][k] directly ----------------
__global__ __launch_bounds__(256) void build_At(const float* __restrict__ x)
{
    __shared__ float t[32][33];
    int mb = blockIdx.x, kb = blockIdx.y;
    int tx = threadIdx.x & 31, ty = threadIdx.x >> 5;
    int p = mb * 32 + tx;
    int b = p >> 12;
#pragma unroll
    for (int i = 0; i < 32; i += 8) {
        int k = kb * 32 + ty + i;
        int c = k / 3, n = k - 3 * c;
        const float* xp = x + ((size_t)b * Cn + c) * HWn;
        int base = n * Mn + p;
        float acc = g_swgt[base]               * xp[g_sidx[base]]
                  + g_swgt[Np * Mn + base]     * xp[g_sidx[Np * Mn + base]]
                  + g_swgt[2 * Np * Mn + base] * xp[g_sidx[2 * Np * Mn + base]]
                  + g_swgt[3 * Np * Mn + base] * xp[g_sidx[3 * Np * Mn + base]];
        t[ty + i][tx] = acc;
    }
    __syncthreads();
#pragma unroll
    for (int i = 0; i < 32; i += 8)
        g_At[(size_t)(mb * 32 + ty + i) * K1 + kb * 32 + tx] = t[tx][ty + i];
}

// ---------------- bf16 split helpers ----------------
__device__ __forceinline__ uint32_t pack_bf2(__nv_bfloat16 a, __nv_bfloat16 b) {
    __nv_bfloat162 t = __halves2bfloat162(a, b);
    return *reinterpret_cast<uint32_t*>(&t);
}
__device__ __forceinline__ void cvt_hilo4(float4 v, uint32_t* hi, uint32_t* lo) {
    __nv_bfloat16 hx = __float2bfloat16_rn(v.x);
    __nv_bfloat16 hy = __float2bfloat16_rn(v.y);
    __nv_bfloat16 hz = __float2bfloat16_rn(v.z);
    __nv_bfloat16 hw = __float2bfloat16_rn(v.w);
    hi[0] = pack_bf2(hx, hy);
    hi[1] = pack_bf2(hz, hw);
    lo[0] = pack_bf2(__float2bfloat16_rn(v.x - __bfloat162float(hx)),
                     __float2bfloat16_rn(v.y - __bfloat162float(hy)));
    lo[1] = pack_bf2(__float2bfloat16_rn(v.z - __bfloat162float(hz)),
                     __float2bfloat16_rn(v.w - __bfloat162float(hw)));
}
__device__ __forceinline__ void mma_bf16(float* c, const uint32_t* a, const uint32_t* b) {
    asm volatile(
        "mma.sync.aligned.m16n8k16.row.col.f32.bf16.bf16.f32 "
        "{%0,%1,%2,%3}, {%4,%5,%6,%7}, {%8,%9}, {%0,%1,%2,%3};"
        : "+f"(c[0]), "+f"(c[1]), "+f"(c[2]), "+f"(c[3])
        : "r"(a[0]), "r"(a[1]), "r"(a[2]), "r"(a[3]), "r"(b[0]), "r"(b[1]));
}
__device__ __forceinline__ void ldsm_x4(uint32_t* r, uint32_t addr) {
    asm volatile("ldmatrix.sync.aligned.m8n8.x4.shared.b16 {%0,%1,%2,%3}, [%4];"
                 : "=r"(r[0]), "=r"(r[1]), "=r"(r[2]), "=r"(r[3]) : "r"(addr));
}

// ---------------- mma.sync bf16 split GEMM, ldmatrix fragments ----------------
// tile 128x128, K-chunk 32. D[m][n] = sum_k A[m][k]*Bw[n][k].
// EPI 0: row-major store. EPI 1: Cd = mulv*(acc+bias). EPI 2: NCHW + bias + residual.
#define SROW 40     // bf16 units per smem row (80B stride -> conflict-free ldmatrix)

template <int EPI>
__global__ __launch_bounds__(256) void mma_gemm(const float* __restrict__ A,
                                                const float* __restrict__ Bw,
                                                float* __restrict__ Cd, int K,
                                                const float* __restrict__ bias,
                                                const float* __restrict__ mulv,
                                                const float* __restrict__ addv)
{
    __shared__ __nv_bfloat16 As_hi[128 * SROW];
    __shared__ __nv_bfloat16 As_lo[128 * SROW];
    __shared__ __nv_bfloat16 Bs_hi[128 * SROW];
    __shared__ __nv_bfloat16 Bs_lo[128 * SROW];

    const int tid  = threadIdx.x;
    const int lane = tid & 31;
    const int wrp  = tid >> 5;
    const int wm   = wrp >> 1;          // 0..3  (m quadrant, 32 rows)
    const int wn   = wrp & 1;           // 0..1  (n half, 64 cols)
    const int g    = lane >> 2;         // 0..7
    const int t2   = (lane & 3) * 2;    // 0,2,4,6
    const int m0   = blockIdx.x * 128;
    const int n0   = blockIdx.y * 128;

    const int srow = tid >> 1;                // staging row 0..127
    const int skb  = (tid & 1) * 16;          // staging k-base 0 or 16

    const uint32_t sAhi = smem_u32(As_hi), sAlo = smem_u32(As_lo);
    const uint32_t sBhi = smem_u32(Bs_hi), sBlo = smem_u32(Bs_lo);

    // ldmatrix source offsets (bytes), fixed per thread modulo ks*32
    const uint32_t aoffA = (uint32_t)((wm * 32 + (lane & 15)) * SROW + (lane >> 4) * 8) * 2;
    const int mtstep = 16 * SROW * 2;
    const uint32_t boffB = (uint32_t)((wn * 64 + (lane & 7) + ((lane >> 4) & 1) * 8) * SROW
                                      + ((lane >> 3) & 1) * 8) * 2;
    const int ntstep = 16 * SROW * 2;

    float acc[2][8][4];
#pragma unroll
    for (int i = 0; i < 2; i++)
#pragma unroll
        for (int j = 0; j < 8; j++)
#pragma unroll
            for (int q = 0; q < 4; q++) acc[i][j][q] = 0.f;

    float4 pa[4], pb[4];
    const int NCH = K >> 5;

    // prefetch chunk 0
#pragma unroll
    for (int j = 0; j < 4; j++) {
        pa[j] = *reinterpret_cast<const float4*>(&A [(size_t)(m0 + srow) * K + skb + j * 4]);
        pb[j] = *reinterpret_cast<const float4*>(&Bw[(size_t)(n0 + srow) * K + skb + j * 4]);
    }

    for (int ch = 0; ch < NCH; ch++) {
        __syncthreads();                       // consumers of previous chunk done
#pragma unroll
        for (int j = 0; j < 4; j++) {
            uint32_t hi[2], lo[2];
            int off = srow * SROW + skb + j * 4;
            cvt_hilo4(pa[j], hi, lo);
            *reinterpret_cast<uint2*>(&As_hi[off]) = make_uint2(hi[0], hi[1]);
            *reinterpret_cast<uint2*>(&As_lo[off]) = make_uint2(lo[0], lo[1]);
            cvt_hilo4(pb[j], hi, lo);
            *reinterpret_cast<uint2*>(&Bs_hi[off]) = make_uint2(hi[0], hi[1]);
            *reinterpret_cast<uint2*>(&Bs_lo[off]) = make_uint2(lo[0], lo[1]);
        }
        __syncthreads();

        if (ch + 1 < NCH) {                    // prefetch next chunk during mma phase
            int k0 = (ch + 1) << 5;
#pragma unroll
            for (int j = 0; j < 4; j++) {
                pa[j] = *reinterpret_cast<const float4*>(&A [(size_t)(m0 + srow) * K + k0 + skb + j * 4]);
                pb[j] = *reinterpret_cast<const float4*>(&Bw[(size_t)(n0 + srow) * K + k0 + skb + j * 4]);
            }
        }

#pragma unroll
        for (int ks = 0; ks < 2; ks++) {
            const uint32_t kso = (uint32_t)(ks * 16 * 2);   // byte offset within row
            uint32_t ah[2][4], al[2][4];
#pragma unroll
            for (int mt = 0; mt < 2; mt++) {
                ldsm_x4(ah[mt], sAhi + aoffA + mt * mtstep + kso);
                ldsm_x4(al[mt], sAlo + aoffA + mt * mtstep + kso);
            }
#pragma unroll
            for (int ntp = 0; ntp < 4; ntp++) {
                uint32_t bh[4], bl[4];
                ldsm_x4(bh, sBhi + boffB + ntp * ntstep + kso);
                ldsm_x4(bl, sBlo + boffB + ntp * ntstep + kso);
#pragma unroll
                for (int half = 0; half < 2; half++) {
                    int nt = ntp * 2 + half;
#pragma unroll
                    for (int mt = 0; mt < 2; mt++) {
                        mma_bf16(acc[mt][nt], ah[mt], &bh[half * 2]);
                        mma_bf16(acc[mt][nt], ah[mt], &bl[half * 2]);
                        mma_bf16(acc[mt][nt], al[mt], &bh[half * 2]);
                    }
                }
            }
        }
    }

    // ---------------- epilogue ----------------
#pragma unroll
    for (int mt = 0; mt < 2; mt++) {
        int mrow = m0 + wm * 32 + mt * 16 + g;           // rows mrow, mrow+8
#pragma unroll
        for (int nt = 0; nt < 8; nt++) {
            int ncol = n0 + wn * 64 + nt * 8 + t2;
            float c0 = acc[mt][nt][0], c1 = acc[mt][nt][1];
            float c2 = acc[mt][nt][2], c3 = acc[mt][nt][3];
            if (EPI == 0) {
                *reinterpret_cast<float2*>(&Cd[(size_t) mrow      * Cn + ncol]) = make_float2(c0, c1);
                *reinterpret_cast<float2*>(&Cd[(size_t)(mrow + 8) * Cn + ncol]) = make_float2(c2, c3);
            } else if (EPI == 1) {
                float b0 = bias[ncol], b1 = bias[ncol + 1];
                float2 u0 = *reinterpret_cast<const float2*>(&mulv[(size_t) mrow      * Cn + ncol]);
                float2 u1 = *reinterpret_cast<const float2*>(&mulv[(size_t)(mrow + 8) * Cn + ncol]);
                *reinterpret_cast<float2*>(&Cd[(size_t) mrow      * Cn + ncol]) =
                    make_float2(u0.x * (c0 + b0), u0.y * (c1 + b1));
                *reinterpret_cast<float2*>(&Cd[(size_t)(mrow + 8) * Cn + ncol]) =
                    make_float2(u1.x * (c2 + b0), u1.y * (c3 + b1));
            } else {
                float b0 = bias[ncol], b1 = bias[ncol + 1];
                int bq = mrow >> 12, hw = mrow & 4095;
                size_t o0 = ((size_t)(bq * Cn + ncol)) * HWn + hw;
                size_t o1 = o0 + HWn;                    // ncol+1
                Cd[o0]     = c0 + b0 + addv[o0];
                Cd[o1]     = c1 + b1 + addv[o1];
                Cd[o0 + 8] = c2 + b0 + addv[o0 + 8];     // row mrow+8 -> hw+8
                Cd[o1 + 8] = c3 + b1 + addv[o1 + 8];
            }
        }
    }
}

// ---------------- BN (batch stats) ----------------
__global__ void bn_part()
{
    int c = threadIdx.x;
    int r0 = blockIdx.x * 256;
    float s = 0.f, s2 = 0.f;
    for (int r = 0; r < 256; r++) {
        float v = g_pre[(size_t)(r0 + r) * Cn + c];
        s += v; s2 += v * v;
    }
    g_bnp [blockIdx.x * Cn + c] = s;
    g_bnp2[blockIdx.x * Cn + c] = s2;
}

__global__ void bn_final(const float* __restrict__ gamma, const float* __restrict__ beta)
{
    int c = threadIdx.x;
    float s = 0.f, s2 = 0.f;
    for (int r = 0; r < 128; r++) { s += g_bnp[r * Cn + c]; s2 += g_bnp2[r * Cn + c]; }
    float mean = s / (float)Mn;
    float var  = s2 / (float)Mn - mean * mean;
    float sc = gamma[c] * rsqrtf(var + EPSb);
    g_bnsc[c] = sc;
    g_bnsh[c] = beta[c] - mean * sc;
}

__global__ void bn_apply()
{
    size_t i = (size_t)blockIdx.x * 256 + threadIdx.x;
    int c = threadIdx.x;
    float v = g_pre[i] * g_bnsc[c] + g_bnsh[c];
    g_y[i] = v / (1.f + expf(-v));
}

// ---------------- depthwise convs ----------------
__global__ __launch_bounds__(256) void dw5_kernel(const float* __restrict__ bias)
{
    int q = threadIdx.x & 63, pl = threadIdx.x >> 6;
    int p = blockIdx.x * 4 + pl;
    int b = p >> 12, hw = p & 4095, h = hw >> 6, w = hw & 63;
    int c = q * 4;
    float4 acc = make_float4(bias[c], bias[c + 1], bias[c + 2], bias[c + 3]);
    const float* base = g_y + ((size_t)b << 12) * Cn;
#pragma unroll
    for (int kh = 0; kh < 5; kh++) {
        int hh = h + kh - 2;
        if ((unsigned)hh >= (unsigned)Hn) continue;
#pragma unroll
        for (int kw = 0; kw < 5; kw++) {
            int w2 = w + kw - 2;
            if ((unsigned)w2 >= (unsigned)Wn) continue;
            float4 v  = *reinterpret_cast<const float4*>(&base[(size_t)(hh * Wn + w2) * Cn + c]);
            float4 wv = *reinterpret_cast<const float4*>(&g_w5T[(kh * 5 + kw) * Cn + c]);
            acc.x += v.x * wv.x; acc.y += v.y * wv.y;
            acc.z += v.z * wv.z; acc.w += v.w * wv.w;
        }
    }
    *reinterpret_cast<float4*>(&g_t1[(size_t)p * Cn + c]) = acc;
}

__global__ __launch_bounds__(256) void dw7_kernel(const float* __restrict__ bias)
{
    int q = threadIdx.x & 63, pl = threadIdx.x >> 6;
    int p = blockIdx.x * 4 + pl;
    int b = p >> 12, hw = p & 4095, h = hw >> 6, w = hw & 63;
    int c = q * 4;
    float4 acc = make_float4(bias[c], bias[c + 1], bias[c + 2], bias[c + 3]);
    const float* base = g_t1 + ((size_t)b << 12) * Cn;
#pragma unroll
    for (int kh = 0; kh < 7; kh++) {
        int hh = h + (kh - 3) * 3;
        if ((unsigned)hh >= (unsigned)Hn) continue;
#pragma unroll
        for (int kw = 0; kw < 7; kw++) {
            int w2 = w + (kw - 3) * 3;
            if ((unsigned)w2 >= (unsigned)Wn) continue;
            float4 v  = *reinterpret_cast<const float4*>(&base[(size_t)(hh * Wn + w2) * Cn + c]);
            float4 wv = *reinterpret_cast<const float4*>(&g_w7T[(kh * 7 + kw) * Cn + c]);
            acc.x += v.x * wv.x; acc.y += v.y * wv.y;
            acc.z += v.z * wv.z; acc.w += v.w * wv.w;
        }
    }
    *reinterpret_cast<float4*>(&g_t2[(size_t)p * Cn + c]) = acc;
}

// ---------------- launch ----------------
extern "C" void kernel_launch(void* const* d_in, const int* in_sizes, int n_in,
                              void* d_out, int out_size)
{
    const float* x   = (const float*)d_in[0];
    const float* p_w = (const float*)d_in[1];
    const float* p_b = (const float*)d_in[2];
    const float* akw = (const float*)d_in[3];
    const float* gam = (const float*)d_in[4];
    const float* bet = (const float*)d_in[5];
    const float* l0w = (const float*)d_in[6];
    const float* l0b = (const float*)d_in[7];
    const float* lsw = (const float*)d_in[8];
    const float* lsb = (const float*)d_in[9];
    const float* l1w = (const float*)d_in[10];
    const float* l1b = (const float*)d_in[11];
    const float* cvw = (const float*)d_in[12];
    const float* cvb = (const float*)d_in[13];
    float* out = (float*)d_out;

    float* off_p; cudaGetSymbolAddress((void**)&off_p, g_off);
    float* At_p;  cudaGetSymbolAddress((void**)&At_p,  g_At);
    float* pre_p; cudaGetSymbolAddress((void**)&pre_p, g_pre);
    float* y_p;   cudaGetSymbolAddress((void**)&y_p,   g_y);
    float* t2_p;  cudaGetSymbolAddress((void**)&t2_p,  g_t2);
    float* lka_p; cudaGetSymbolAddress((void**)&lka_p, g_lka);

    prep_weights<<<(25 * Cn + 49 * Cn + 255) / 256, 256>>>(l0w, lsw);
    offs_kernel<<<Mn / 128, 128>>>(x, p_w, p_b, off_p);
    sample_prep<<<(Np * Mn + 255) / 256, 256>>>(off_p);
    build_At<<<dim3(Mn / 32, K1 / 32), 256>>>(x);

    // GEMM1: pre[m][o] = sum_k xoff[m][k] * akw[o][k]   (K=768)  -> launch #5 (ncu -s 5)
    mma_gemm<0><<<dim3(Mn / 128, Cn / 128), 256>>>(At_p, akw, pre_p, K1,
                                                   nullptr, nullptr, nullptr);
    bn_part<<<128, 256>>>();
    bn_final<<<1, 256>>>(gam, bet);
    bn_apply<<<Mn, 256>>>();

    dw5_kernel<<<Mn / 4, 256>>>(l0b);
    dw7_kernel<<<Mn / 4, 256>>>(lsb);

    // GEMM2: lka = y * (t2 @ l1w^T + b)   (K=256)
    mma_gemm<1><<<dim3(Mn / 128, Cn / 128), 256>>>(t2_p, l1w, lka_p, Cn,
                                                   l1b, y_p, nullptr);
    // GEMM3: out = lka @ cvw^T + b + x   (NCHW, K=256)
    mma_gemm<2><<<dim3(Mn / 128, Cn / 128), 256>>>(lka_p, cvw, out, Cn,
                                                   cvb, nullptr, (float*)x);
}